// round 3
// baseline (speedup 1.0000x reference)
#include <cuda_runtime.h>

// ---------------- problem constants ----------------
#define NJ     21          // joints
#define CD     235         // channels
#define HW     4096        // 64*64
#define BATCH  128
#define HD     128         // heads*fo
#define NH     4
#define FO     32

// ---------------- kernel-1 tiling ----------------
#define PT     2048        // p-tile staged in shared
#define NKT    (HW / PT)   // 2
#define NCH    (PT / 128)  // 16 chunks of 128 p per tile
#define QPITCH 240
#define NPASS  15          // ceil(235/16) c-passes (16 c per pass)

typedef unsigned long long ull;

// scratch (static device globals: no allocation at runtime)
__device__ float g_q[(size_t)BATCH * NJ * CD];
__device__ float g_stats[NJ * 2];   // mean, rstd per joint

// ---------------- f32x2 helpers ----------------
__device__ __forceinline__ void fma2(ull &a, ull x, ull y) {
    asm("fma.rn.f32x2 %0, %1, %2, %0;" : "+l"(a) : "l"(x), "l"(y));
}
__device__ __forceinline__ float2 up2(ull a) {
    float2 r;
    asm("mov.b64 {%0, %1}, %2;" : "=f"(r.x), "=f"(r.y) : "l"(a));
    return r;
}

// load 8 c-columns' worth of 16B f fragments (coalesced across lanes)
__device__ __forceinline__ void loadf8(ulonglong2 *A, const float *fp, int cb) {
#pragma unroll
    for (int j = 0; j < 8; j++) {
        if (cb + j < CD) {
            A[j] = *(const ulonglong2 *)(fp + (size_t)j * HW);
        } else {
            A[j].x = 0ull; A[j].y = 0ull;
        }
    }
}

template <int NW>
__device__ __forceinline__ void rows_compute(ull (&acc)[NW][8],
                                             const float *tp,
                                             const ulonglong2 *A) {
#pragma unroll
    for (int ni = 0; ni < NW; ni++) {
        ulonglong2 tt = *(const ulonglong2 *)(tp + ni * PT);  // LDS.128, conflict-free
#pragma unroll
        for (int cj = 0; cj < 8; cj++) {
            fma2(acc[ni][cj], A[cj].x, tt.x);
            fma2(acc[ni][cj], A[cj].y, tt.y);
        }
    }
}

// one c-pass: accumulate q[n0..n0+NW-1][cb..cb+7] over this k-tile
template <int NW>
__device__ __forceinline__ void do_pass(const float *fptr,   // fb + cb*HW + kt*PT + lane*4
                                        const float *tptr,   // t_s + n0*PT + lane*4
                                        float *q_s,
                                        int n0, int cb, int lane) {
    ull acc[NW][8];
#pragma unroll
    for (int i = 0; i < NW; i++)
#pragma unroll
        for (int j = 0; j < 8; j++) acc[i][j] = 0ull;

    ulonglong2 A[8], Bv[8];
    const float *fp = fptr;
    const float *tp = tptr;
    loadf8(A, fp, cb);                       // chunk 0
#pragma unroll 1
    for (int it = 0; it < NCH / 2; it++) {
        loadf8(Bv, fp + 128, cb);            // prefetch odd chunk
        rows_compute<NW>(acc, tp, A);        // even chunk
        if (it < NCH / 2 - 1) loadf8(A, fp + 256, cb);  // prefetch next even
        rows_compute<NW>(acc, tp + 128, Bv); // odd chunk
        fp += 256;
        tp += 256;
    }

    // reduce lanes (p-partials) and accumulate into shared q
#pragma unroll
    for (int ni = 0; ni < NW; ni++) {
#pragma unroll
        for (int cj = 0; cj < 8; cj++) {
            float2 v2 = up2(acc[ni][cj]);
            float v = v2.x + v2.y;
            v += __shfl_down_sync(0xffffffffu, v, 16);
            v += __shfl_down_sync(0xffffffffu, v, 8);
            v += __shfl_down_sync(0xffffffffu, v, 4);
            v += __shfl_down_sync(0xffffffffu, v, 2);
            v += __shfl_down_sync(0xffffffffu, v, 1);
            if (lane == 0 && (cb + cj) < CD)
                q_s[(n0 + ni) * QPITCH + cb + cj] += v;   // (n,c) owned by this warp only
        }
    }
}

// ---------------- kernel 1: q[b,n,c] = sum_p t[b,n,p] * f[b,c,p] ----------------
extern "C" __global__ void __launch_bounds__(256, 1)
qgemm_kernel(const float *__restrict__ f, const float *__restrict__ t) {
    extern __shared__ float sm[];
    float *t_s = sm;                 // NJ * PT
    float *q_s = sm + NJ * PT;       // NJ * QPITCH

    const int b = blockIdx.x;
    const int tid = threadIdx.x;
    const int warp = tid >> 5;
    const int lane = tid & 31;
    // warp -> (c-group, n-group): cg = warp&1, ng = warp>>1 (balances SMSPs)
    const int cg = warp & 1;
    const int ng = warp >> 1;
    const int n0 = (ng == 0) ? 0 : 6 + (ng - 1) * 5;   // 0,6,11,16
    const int nw = (ng == 0) ? 6 : 5;

    for (int i = tid; i < NJ * QPITCH; i += 256) q_s[i] = 0.f;

    const float *fb = f + (size_t)b * CD * HW;
    const float *tb = t + (size_t)b * NJ * HW;

    for (int kt = 0; kt < NKT; kt++) {
        __syncthreads();  // protect t_s against previous-tile readers
        // cooperative, coalesced t-tile load: 21 x PT
        for (int i = tid; i < NJ * (PT / 4); i += 256) {
            int row = i / (PT / 4);
            int col = i % (PT / 4);
            ((float4 *)(t_s + (size_t)row * PT))[col] =
                ((const float4 *)(tb + (size_t)row * HW + (size_t)kt * PT))[col];
        }
        __syncthreads();

        for (int pass = 0; pass < NPASS; pass++) {
            const int cb = pass * 16 + cg * 8;
            const float *fptr = fb + (size_t)cb * HW + (size_t)kt * PT + lane * 4;
            const float *tptr = t_s + (size_t)n0 * PT + lane * 4;
            if (nw == 6) do_pass<6>(fptr, tptr, q_s, n0, cb, lane);
            else         do_pass<5>(fptr, tptr, q_s, n0, cb, lane);
        }
    }

    __syncthreads();
    for (int i = tid; i < NJ * CD; i += 256) {
        int n = i / CD, c = i % CD;
        g_q[((size_t)b * NJ + n) * CD + c] = q_s[n * QPITCH + c];
    }
}

// ---------------- kernel 2: BN stats per joint over (B, C) ----------------
extern "C" __global__ void __launch_bounds__(256)
bn_stats_kernel() {
    const int n = blockIdx.x;
    const int tid = threadIdx.x;
    float s = 0.f, s2 = 0.f;
    for (int b = 0; b < BATCH; b++) {
        const float *row = g_q + ((size_t)b * NJ + n) * CD;
        for (int c = tid; c < CD; c += 256) {
            float v = row[c];
            s += v; s2 += v * v;
        }
    }
    __shared__ float rs[256], rs2[256];
    rs[tid] = s; rs2[tid] = s2;
    __syncthreads();
    for (int st = 128; st > 0; st >>= 1) {
        if (tid < st) { rs[tid] += rs[tid + st]; rs2[tid] += rs2[tid + st]; }
        __syncthreads();
    }
    if (tid == 0) {
        const float inv = 1.f / (float)(BATCH * CD);
        float mean = rs[0] * inv;
        float var = rs2[0] * inv - mean * mean;
        g_stats[n * 2 + 0] = mean;
        g_stats[n * 2 + 1] = rsqrtf(var + 1e-5f);
    }
}

// ---------------- kernel 3: BN apply + LeakyReLU + GAT + ChebConv (fused, per batch) ----------------
extern "C" __global__ void __launch_bounds__(256)
fused_kernel(const float *__restrict__ gamma, const float *__restrict__ beta,
             const float *__restrict__ gat_w, const float *__restrict__ att_src,
             const float *__restrict__ att_dst, const float *__restrict__ gat_bias,
             const float *__restrict__ cheb_w, const float *__restrict__ cheb_bias,
             const float *__restrict__ adj, const int *__restrict__ e_src,
             const int *__restrict__ e_dst, int nE, float *__restrict__ out) {
    __shared__ float qa[NJ][236];
    __shared__ float h[NJ][HD];
    __shared__ float x[NJ][HD];
    __shared__ float asrc[NJ][NH], adst[NJ][NH];
    __shared__ float ee[64][NH];
    __shared__ float mm[NJ][NH], dd[NJ][NH];
    __shared__ float xw0[NJ][3], xw1[NJ][3];
    __shared__ float dinv[NJ];
    __shared__ int es[64], ed[64];
    __shared__ float stats_s[NJ][2];

    const int b = blockIdx.x;
    const int tid = threadIdx.x;
    if (nE > 64) nE = 64;

    if (tid < NJ * 2) ((float *)stats_s)[tid] = g_stats[tid];
    if (tid < nE) { es[tid] = e_src[tid]; ed[tid] = e_dst[tid]; }
    if (tid < NJ) {
        float s = 0.f;
        for (int j = 0; j < NJ; j++) s += adj[tid * NJ + j];
        dinv[tid] = rsqrtf(s);
    }
    __syncthreads();

    // BN + LeakyReLU(0.1) into shared
    for (int i = tid; i < NJ * CD; i += 256) {
        int n = i / CD, c = i % CD;
        float v = g_q[((size_t)b * NJ + n) * CD + c];
        v = (v - stats_s[n][0]) * stats_s[n][1] * gamma[n] + beta[n];
        qa[n][c] = (v >= 0.f) ? v : 0.1f * v;
    }
    __syncthreads();

    // h = qa @ gat_w : thread owns fixed j, strided n (W stays L1-hot)
    {
        const int j = tid & 127;
        const int g = tid >> 7;    // 0/1
        for (int n = g; n < NJ; n += 2) {
            float s = 0.f;
            for (int c = 0; c < CD; c++) s = fmaf(qa[n][c], gat_w[c * HD + j], s);
            h[n][j] = s;
        }
    }
    __syncthreads();

    // attention logits
    if (tid < NJ * NH) {
        int n = tid / NH, hh = tid % NH;
        float s1 = 0.f, s2 = 0.f;
        for (int k = 0; k < FO; k++) {
            float hv = h[n][hh * FO + k];
            s1 = fmaf(hv, att_src[hh * FO + k], s1);
            s2 = fmaf(hv, att_dst[hh * FO + k], s2);
        }
        asrc[n][hh] = s1; adst[n][hh] = s2;
    }
    __syncthreads();

    if (tid < nE * NH) {
        int e = tid / NH, hh = tid % NH;
        float v = asrc[es[e]][hh] + adst[ed[e]][hh];
        ee[e][hh] = (v >= 0.f) ? v : 0.2f * v;   // GAT negative_slope=0.2
    }
    __syncthreads();

    // per-destination softmax stats
    if (tid < NJ * NH) {
        int n = tid / NH, hh = tid % NH;
        float m = -1e30f;
        for (int e = 0; e < nE; e++)
            if (ed[e] == n) m = fmaxf(m, ee[e][hh]);
        float den = 0.f;
        for (int e = 0; e < nE; e++)
            if (ed[e] == n) den += __expf(ee[e][hh] - m);
        mm[n][hh] = m; dd[n][hh] = den;
    }
    __syncthreads();

    // aggregate messages + bias
    for (int i = tid; i < NJ * HD; i += 256) {
        int n = i >> 7, j = i & 127, hh = j >> 5;
        float s = 0.f;
        float m = mm[n][hh];
        for (int e = 0; e < nE; e++)
            if (ed[e] == n) s = fmaf(__expf(ee[e][hh] - m), h[es[e]][j], s);
        x[n][j] = s / dd[n][hh] + gat_bias[j];
    }
    __syncthreads();

    // Cheb: xw0 = x@W0, xw1 = x@W1
    if (tid < NJ * 3 * 2) {
        int k = tid / (NJ * 3);
        int r = tid % (NJ * 3);
        int n = r / 3, o = r % 3;
        const float *w = cheb_w + (size_t)k * HD * 3;
        float s = 0.f;
        for (int j = 0; j < HD; j++) s = fmaf(x[n][j], w[j * 3 + o], s);
        if (k == 0) xw0[n][o] = s; else xw1[n][o] = s;
    }
    __syncthreads();

    // y = xw0 + (I - d A d) @ xw1 + bias
    if (tid < NJ * 3) {
        int m = tid / 3, o = tid % 3;
        float s = xw0[m][o] + xw1[m][o];
        for (int n = 0; n < NJ; n++)
            s -= dinv[m] * adj[m * NJ + n] * dinv[n] * xw1[n][o];
        out[(size_t)b * NJ * 3 + tid] = s + cheb_bias[o];
    }
}

// ---------------- launch ----------------
extern "C" void kernel_launch(void *const *d_in, const int *in_sizes, int n_in,
                              void *d_out, int out_size) {
    const float *feature_s = (const float *)d_in[0];
    const float *target_s  = (const float *)d_in[1];
    const float *bn_gamma  = (const float *)d_in[2];
    const float *bn_beta   = (const float *)d_in[3];
    const float *gat_w     = (const float *)d_in[4];
    const float *att_src   = (const float *)d_in[5];
    const float *att_dst   = (const float *)d_in[6];
    const float *gat_bias  = (const float *)d_in[7];
    const float *cheb_w    = (const float *)d_in[8];
    const float *cheb_bias = (const float *)d_in[9];
    const float *adj       = (const float *)d_in[10];
    const int   *e_src     = (const int *)d_in[11];
    const int   *e_dst     = (const int *)d_in[12];
    const int nE = in_sizes[11];
    float *out = (float *)d_out;

    const size_t smem1 = (size_t)(NJ * PT + NJ * QPITCH) * sizeof(float);  // ~188 KB
    cudaFuncSetAttribute(qgemm_kernel, cudaFuncAttributeMaxDynamicSharedMemorySize,
                         (int)smem1);

    qgemm_kernel<<<BATCH, 256, smem1>>>(feature_s, target_s);
    bn_stats_kernel<<<NJ, 256>>>();
    fused_kernel<<<BATCH, 256>>>(bn_gamma, bn_beta, gat_w, att_src, att_dst,
                                 gat_bias, cheb_w, cheb_bias, adj, e_src, e_dst,
                                 nE, out);
    (void)n_in; (void)out_size; (void)in_sizes;
}

// round 5
// speedup vs baseline: 1.0885x; 1.0885x over previous
#include <cuda_runtime.h>

// ---------------- problem constants ----------------
#define NJ     21          // joints
#define CD     235         // channels
#define HW     4096        // 64*64
#define BATCH  128
#define HD     128         // heads*fo
#define NH     4
#define FO     32

// ---------------- kernel-1 tiling ----------------
#define PT     2048        // p-tile staged in shared
#define NKT    (HW / PT)   // 2
#define NCH    (PT / 128)  // 16 chunks of 128 p per tile
#define QPITCH 240
#define NPASS  15          // 15 passes x 16 c = 240 >= 235
#define THREADS 448        // 14 warps = 2 cg x 7 ng
#define NWR    3           // rows per warp (7 ng x 3 = 21)

typedef unsigned long long ull;

// scratch (static device globals: no allocation at runtime)
__device__ float g_q[(size_t)BATCH * NJ * CD];
__device__ float g_psum[2 * NJ * BATCH];   // [kind][joint][batch] partial sum / sumsq
__device__ float g_stats[NJ * 2];          // mean, rstd per joint

// ---------------- f32x2 helpers ----------------
__device__ __forceinline__ void fma2(ull &a, ull x, ull y) {
    asm("fma.rn.f32x2 %0, %1, %2, %0;" : "+l"(a) : "l"(x), "l"(y));
}
__device__ __forceinline__ float2 up2(ull a) {
    float2 r;
    asm("mov.b64 {%0, %1}, %2;" : "=f"(r.x), "=f"(r.y) : "l"(a));
    return r;
}

// load 8 c-columns' worth of 16B f fragments (coalesced across lanes)
__device__ __forceinline__ void loadf8(ulonglong2 *A, const float *fp, int cb) {
#pragma unroll
    for (int j = 0; j < 8; j++) {
        if (cb + j < CD) {
            A[j] = *(const ulonglong2 *)(fp + (size_t)j * HW);
        } else {
            A[j].x = 0ull; A[j].y = 0ull;
        }
    }
}

__device__ __forceinline__ void rows_compute(ull (&acc)[NWR][8],
                                             const float *tp,
                                             const ulonglong2 *A) {
#pragma unroll
    for (int ni = 0; ni < NWR; ni++) {
        ulonglong2 tt = *(const ulonglong2 *)(tp + ni * PT);  // LDS.128, conflict-free
#pragma unroll
        for (int cj = 0; cj < 8; cj++) {
            fma2(acc[ni][cj], A[cj].x, tt.x);
            fma2(acc[ni][cj], A[cj].y, tt.y);
        }
    }
}

// one c-pass: accumulate q[n0..n0+2][cb..cb+7] over this k-tile
__device__ __forceinline__ void do_pass(const float *fptr,   // fb + cb*HW + kt*PT + lane*4
                                        const float *tptr,   // t_s + n0*PT + lane*4
                                        float *q_s,
                                        int n0, int cb, int lane) {
    ull acc[NWR][8];
#pragma unroll
    for (int i = 0; i < NWR; i++)
#pragma unroll
        for (int j = 0; j < 8; j++) acc[i][j] = 0ull;

    ulonglong2 A[8], Bv[8];
    const float *fp = fptr;
    const float *tp = tptr;
    loadf8(A, fp, cb);                       // chunk 0
#pragma unroll 1
    for (int it = 0; it < NCH / 2; it++) {
        loadf8(Bv, fp + 128, cb);            // prefetch odd chunk
        rows_compute(acc, tp, A);            // even chunk
        if (it < NCH / 2 - 1) loadf8(A, fp + 256, cb);  // prefetch next even
        rows_compute(acc, tp + 128, Bv);     // odd chunk
        fp += 256;
        tp += 256;
    }

    // reduce lanes (p-partials) and accumulate into shared q
#pragma unroll
    for (int ni = 0; ni < NWR; ni++) {
#pragma unroll
        for (int cj = 0; cj < 8; cj++) {
            float2 v2 = up2(acc[ni][cj]);
            float v = v2.x + v2.y;
            v += __shfl_down_sync(0xffffffffu, v, 16);
            v += __shfl_down_sync(0xffffffffu, v, 8);
            v += __shfl_down_sync(0xffffffffu, v, 4);
            v += __shfl_down_sync(0xffffffffu, v, 2);
            v += __shfl_down_sync(0xffffffffu, v, 1);
            if (lane == 0 && (cb + cj) < CD)
                q_s[(n0 + ni) * QPITCH + cb + cj] += v;   // (n,c) owned by this warp only
        }
    }
}

// ---------------- kernel 1: q[b,n,c] = sum_p t[b,n,p] * f[b,c,p] ----------------
extern "C" __global__ void __launch_bounds__(THREADS, 1)
qgemm_kernel(const float *__restrict__ f, const float *__restrict__ t) {
    extern __shared__ float sm[];
    float *t_s = sm;                 // NJ * PT
    float *q_s = sm + NJ * PT;       // NJ * QPITCH

    const int b = blockIdx.x;
    const int tid = threadIdx.x;
    const int warp = tid >> 5;
    const int lane = tid & 31;
    const int cg = warp & 1;         // 2 c-groups of 8 columns
    const int ng = warp >> 1;        // 7 n-groups of 3 rows
    const int n0 = ng * NWR;

    for (int i = tid; i < NJ * QPITCH; i += THREADS) q_s[i] = 0.f;

    const float *fb = f + (size_t)b * CD * HW;
    const float *tb = t + (size_t)b * NJ * HW;

    for (int kt = 0; kt < NKT; kt++) {
        __syncthreads();  // protect q_s init / t_s against previous-tile readers
        // cooperative, coalesced t-tile load: 21 x PT
        for (int i = tid; i < NJ * (PT / 4); i += THREADS) {
            int row = i / (PT / 4);
            int col = i % (PT / 4);
            ((float4 *)(t_s + (size_t)row * PT))[col] =
                ((const float4 *)(tb + (size_t)row * HW + (size_t)kt * PT))[col];
        }
        __syncthreads();

        for (int pass = 0; pass < NPASS; pass++) {
            const int cb = pass * 16 + cg * 8;
            const float *fptr = fb + (size_t)cb * HW + (size_t)kt * PT + lane * 4;
            const float *tptr = t_s + (size_t)n0 * PT + lane * 4;
            do_pass(fptr, tptr, q_s, n0, cb, lane);
        }
    }

    __syncthreads();
    // write q to global
    for (int i = tid; i < NJ * CD; i += THREADS) {
        int n = i / CD, c = i % CD;
        g_q[((size_t)b * NJ + n) * CD + c] = q_s[n * QPITCH + c];
    }
    // per-joint partial (sum, sumsq) for BN stats: warp w handles joints w, w+14
    for (int j = warp; j < NJ; j += 14) {
        float s = 0.f, s2 = 0.f;
        for (int c = lane; c < CD; c += 32) {
            float v = q_s[j * QPITCH + c];
            s += v; s2 += v * v;
        }
#pragma unroll
        for (int off = 16; off > 0; off >>= 1) {
            s  += __shfl_down_sync(0xffffffffu, s,  off);
            s2 += __shfl_down_sync(0xffffffffu, s2, off);
        }
        if (lane == 0) {
            g_psum[(0 * NJ + j) * BATCH + b] = s;
            g_psum[(1 * NJ + j) * BATCH + b] = s2;
        }
    }
}

// ---------------- kernel 2: finalize BN stats (1 block) ----------------
extern "C" __global__ void __launch_bounds__(256)
bn_stats_kernel() {
    const int warp = threadIdx.x >> 5;   // 8 warps
    const int lane = threadIdx.x & 31;
    for (int j = warp; j < NJ; j += 8) {
        float s = 0.f, s2 = 0.f;
        for (int b = lane; b < BATCH; b += 32) {
            s  += g_psum[(0 * NJ + j) * BATCH + b];
            s2 += g_psum[(1 * NJ + j) * BATCH + b];
        }
#pragma unroll
        for (int off = 16; off > 0; off >>= 1) {
            s  += __shfl_down_sync(0xffffffffu, s,  off);
            s2 += __shfl_down_sync(0xffffffffu, s2, off);
        }
        if (lane == 0) {
            const float inv = 1.f / (float)(BATCH * CD);
            float mean = s * inv;
            float var = s2 * inv - mean * mean;
            g_stats[j * 2 + 0] = mean;
            g_stats[j * 2 + 1] = rsqrtf(var + 1e-5f);
        }
    }
}

// ---------------- kernel 3: BN apply + LeakyReLU + GAT + ChebConv (fused, per batch) ----------------
extern "C" __global__ void __launch_bounds__(256)
fused_kernel(const float *__restrict__ gamma, const float *__restrict__ beta,
             const float *__restrict__ gat_w, const float *__restrict__ att_src,
             const float *__restrict__ att_dst, const float *__restrict__ gat_bias,
             const float *__restrict__ cheb_w, const float *__restrict__ cheb_bias,
             const float *__restrict__ adj, const int *__restrict__ e_src,
             const int *__restrict__ e_dst, int nE, float *__restrict__ out) {
    __shared__ float qa[NJ][236];
    __shared__ float h[NJ][HD];
    __shared__ float x[NJ][HD];
    __shared__ float asrc[NJ][NH], adst[NJ][NH];
    __shared__ float ee[64][NH];
    __shared__ float mm[NJ][NH], dd[NJ][NH];
    __shared__ float xw0[NJ][3], xw1[NJ][3];
    __shared__ float dinv[NJ];
    __shared__ int es[64], ed[64];
    __shared__ float stats_s[NJ][2];

    const int b = blockIdx.x;
    const int tid = threadIdx.x;
    if (nE > 64) nE = 64;

    if (tid < NJ * 2) ((float *)stats_s)[tid] = g_stats[tid];
    if (tid < nE) { es[tid] = e_src[tid]; ed[tid] = e_dst[tid]; }
    if (tid < NJ) {
        float s = 0.f;
        for (int j = 0; j < NJ; j++) s += adj[tid * NJ + j];
        dinv[tid] = rsqrtf(s);
    }
    __syncthreads();

    // BN + LeakyReLU(0.1) into shared
    for (int i = tid; i < NJ * CD; i += 256) {
        int n = i / CD, c = i % CD;
        float v = g_q[((size_t)b * NJ + n) * CD + c];
        v = (v - stats_s[n][0]) * stats_s[n][1] * gamma[n] + beta[n];
        qa[n][c] = (v >= 0.f) ? v : 0.1f * v;
    }
    __syncthreads();

    // h = qa @ gat_w : thread owns fixed j, strided n (W stays L1-hot)
    {
        const int j = tid & 127;
        const int g = tid >> 7;    // 0/1
        for (int n = g; n < NJ; n += 2) {
            float s = 0.f;
            for (int c = 0; c < CD; c++) s = fmaf(qa[n][c], gat_w[c * HD + j], s);
            h[n][j] = s;
        }
    }
    __syncthreads();

    // attention logits
    if (tid < NJ * NH) {
        int n = tid / NH, hh = tid % NH;
        float s1 = 0.f, s2 = 0.f;
        for (int k = 0; k < FO; k++) {
            float hv = h[n][hh * FO + k];
            s1 = fmaf(hv, att_src[hh * FO + k], s1);
            s2 = fmaf(hv, att_dst[hh * FO + k], s2);
        }
        asrc[n][hh] = s1; adst[n][hh] = s2;
    }
    __syncthreads();

    if (tid < nE * NH) {
        int e = tid / NH, hh = tid % NH;
        float v = asrc[es[e]][hh] + adst[ed[e]][hh];
        ee[e][hh] = (v >= 0.f) ? v : 0.2f * v;   // GAT negative_slope=0.2
    }
    __syncthreads();

    // per-destination softmax stats
    if (tid < NJ * NH) {
        int n = tid / NH, hh = tid % NH;
        float m = -1e30f;
        for (int e = 0; e < nE; e++)
            if (ed[e] == n) m = fmaxf(m, ee[e][hh]);
        float den = 0.f;
        for (int e = 0; e < nE; e++)
            if (ed[e] == n) den += __expf(ee[e][hh] - m);
        mm[n][hh] = m; dd[n][hh] = den;
    }
    __syncthreads();

    // aggregate messages + bias
    for (int i = tid; i < NJ * HD; i += 256) {
        int n = i >> 7, j = i & 127, hh = j >> 5;
        float s = 0.f;
        float m = mm[n][hh];
        for (int e = 0; e < nE; e++)
            if (ed[e] == n) s = fmaf(__expf(ee[e][hh] - m), h[es[e]][j], s);
        x[n][j] = s / dd[n][hh] + gat_bias[j];
    }
    __syncthreads();

    // Cheb: xw0 = x@W0, xw1 = x@W1
    if (tid < NJ * 3 * 2) {
        int k = tid / (NJ * 3);
        int r = tid % (NJ * 3);
        int n = r / 3, o = r % 3;
        const float *w = cheb_w + (size_t)k * HD * 3;
        float s = 0.f;
        for (int j = 0; j < HD; j++) s = fmaf(x[n][j], w[j * 3 + o], s);
        if (k == 0) xw0[n][o] = s; else xw1[n][o] = s;
    }
    __syncthreads();

    // y = xw0 + (I - d A d) @ xw1 + bias
    if (tid < NJ * 3) {
        int m = tid / 3, o = tid % 3;
        float s = xw0[m][o] + xw1[m][o];
        for (int n = 0; n < NJ; n++)
            s -= dinv[m] * adj[m * NJ + n] * dinv[n] * xw1[n][o];
        out[(size_t)b * NJ * 3 + tid] = s + cheb_bias[o];
    }
}

// ---------------- launch ----------------
extern "C" void kernel_launch(void *const *d_in, const int *in_sizes, int n_in,
                              void *d_out, int out_size) {
    const float *feature_s = (const float *)d_in[0];
    const float *target_s  = (const float *)d_in[1];
    const float *bn_gamma  = (const float *)d_in[2];
    const float *bn_beta   = (const float *)d_in[3];
    const float *gat_w     = (const float *)d_in[4];
    const float *att_src   = (const float *)d_in[5];
    const float *att_dst   = (const float *)d_in[6];
    const float *gat_bias  = (const float *)d_in[7];
    const float *cheb_w    = (const float *)d_in[8];
    const float *cheb_bias = (const float *)d_in[9];
    const float *adj       = (const float *)d_in[10];
    const int   *e_src     = (const int *)d_in[11];
    const int   *e_dst     = (const int *)d_in[12];
    const int nE = in_sizes[11];
    float *out = (float *)d_out;

    const size_t smem1 = (size_t)(NJ * PT + NJ * QPITCH) * sizeof(float);  // ~188 KB
    cudaFuncSetAttribute(qgemm_kernel, cudaFuncAttributeMaxDynamicSharedMemorySize,
                         (int)smem1);

    qgemm_kernel<<<BATCH, THREADS, smem1>>>(feature_s, target_s);
    bn_stats_kernel<<<1, 256>>>();
    fused_kernel<<<BATCH, 256>>>(bn_gamma, bn_beta, gat_w, att_src, att_dst,
                                 gat_bias, cheb_w, cheb_bias, adj, e_src, e_dst,
                                 nE, out);
    (void)n_in; (void)out_size; (void)in_sizes;
}